// round 4
// baseline (speedup 1.0000x reference)
#include <cuda_runtime.h>
#include <math_constants.h>

// PhiCell hysteresis scan: out_i = clamp(out_{i-1}, x_i, x_i + 1), x_i = in_i*k.
// Clamp-map composition is associative -> single-pass decoupled-lookback scan.
// Descriptor protocol: CUB-style write-once slots (agg / incl) + release/acquire
// flag, so a reader can never pair a new flag with a stale value.

#define BLOCK 256
#define ITEMS 16
#define CHUNK (BLOCK * ITEMS)   // 4096 elements per tile
#define MAXB  4096

#define FLAG_INV 0
#define FLAG_AGG 1
#define FLAG_PRE 2

struct CH { float L, H; };

__device__ __forceinline__ CH ch_id() {
    CH r; r.L = -CUDART_INF_F; r.H = CUDART_INF_F; return r;
}
// compose: apply a FIRST, then b
__device__ __forceinline__ CH ch_comp(CH a, CH b) {
    CH r;
    r.L = fminf(fmaxf(a.L, b.L), b.H);
    r.H = fminf(fmaxf(a.H, b.L), b.H);
    return r;
}

// write-once descriptor slots + flag (no cudaMalloc allowed)
__device__ float2 g_agg[MAXB];
__device__ float2 g_incl[MAXB];
__device__ int    g_flag[MAXB];

__device__ __forceinline__ void st_flag_release(int i, int f) {
    asm volatile("st.global.release.gpu.b32 [%0], %1;"
                 :: "l"(&g_flag[i]), "r"(f) : "memory");
}
__device__ __forceinline__ int ld_flag_acquire(int i) {
    int f;
    asm volatile("ld.global.acquire.gpu.b32 %0, [%1];"
                 : "=r"(f) : "l"(&g_flag[i]) : "memory");
    return f;
}

__device__ __forceinline__ CH warp_incl_scan(CH v, int lane) {
#pragma unroll
    for (int off = 1; off < 32; off <<= 1) {
        float pl = __shfl_up_sync(0xffffffffu, v.L, off);
        float ph = __shfl_up_sync(0xffffffffu, v.H, off);
        if (lane >= off) { CH p; p.L = pl; p.H = ph; v = ch_comp(p, v); }
    }
    return v;
}

// exclusive composite of all lower-threadIdx threads (identity for t==0)
__device__ CH block_excl_scan(CH v) {
    __shared__ CH ws[BLOCK / 32];
    int lane = threadIdx.x & 31;
    int wid  = threadIdx.x >> 5;

    CH vi = warp_incl_scan(v, lane);
    if (lane == 31) ws[wid] = vi;
    __syncthreads();
    if (wid == 0) {
        CH w = (lane < BLOCK / 32) ? ws[lane] : ch_id();
        w = warp_incl_scan(w, lane);
        if (lane < BLOCK / 32) ws[lane] = w;
    }
    __syncthreads();
    CH wp = (wid > 0) ? ws[wid - 1] : ch_id();

    float pl = __shfl_up_sync(0xffffffffu, vi.L, 1);
    float ph = __shfl_up_sync(0xffffffffu, vi.H, 1);
    CH ve = ch_id();
    if (lane > 0) { ve.L = pl; ve.H = ph; }
    return ch_comp(wp, ve);
}

// reset tile flags before each scan (graph replays reuse g_flag)
__global__ void k_reset(int nb) {
    int i = blockIdx.x * blockDim.x + threadIdx.x;
    if (i < nb) g_flag[i] = FLAG_INV;
}

__global__ void __launch_bounds__(BLOCK)
k_scan(const float* __restrict__ in, const float* __restrict__ kw,
       const float* __restrict__ stt, float* __restrict__ out,
       int n, int out_size) {
    __shared__ CH s_prefix;
    __shared__ CH s_tot;

    float k  = __ldg(kw);
    int bid  = blockIdx.x;
    int base = bid * CHUNK + threadIdx.x * ITEMS;
    const float4* p = reinterpret_cast<const float4*>(in + base);

    // load + scale
    float x[ITEMS];
#pragma unroll
    for (int q = 0; q < ITEMS / 4; q++) {
        float4 x4 = __ldg(&p[q]);
        x[4 * q + 0] = x4.x * k;
        x[4 * q + 1] = x4.y * k;
        x[4 * q + 2] = x4.z * k;
        x[4 * q + 3] = x4.w * k;
    }

    // per-thread composite
    CH c = ch_id();
#pragma unroll
    for (int j = 0; j < ITEMS; j++) {
        float xp = x[j] + 1.0f;
        c.L = fminf(fmaxf(c.L, x[j]), xp);
        c.H = fminf(fmaxf(c.H, x[j]), xp);
    }

    CH e = block_excl_scan(c);   // contains __syncthreads

    // publish tile descriptor ASAP (write-once slot + release flag)
    if (threadIdx.x == BLOCK - 1) {
        CH t = ch_comp(e, c);
        s_tot = t;
        if (bid == 0) {
            g_incl[0] = make_float2(t.L, t.H);
            st_flag_release(0, FLAG_PRE);
        } else {
            g_agg[bid] = make_float2(t.L, t.H);
            st_flag_release(bid, FLAG_AGG);
        }
    }
    __syncthreads();

    // warp 0: decoupled lookback over 32-wide windows of predecessors
    if (threadIdx.x < 32) {
        int lane = threadIdx.x;
        CH run = ch_id();
        if (bid > 0) {
            int tile = bid;
            while (true) {
                int idx = tile - 1 - lane;
                CH v; int fl;
                if (idx >= 0) {
                    do { fl = ld_flag_acquire(idx); } while (fl == FLAG_INV);
                    float2 w = (fl == FLAG_PRE) ? g_incl[idx] : g_agg[idx];
                    v.L = w.x; v.H = w.y;
                } else {
                    v = ch_id(); fl = FLAG_PRE;
                }
                unsigned m = __ballot_sync(0xffffffffu, fl == FLAG_PRE);
                int start = m ? (__ffs(m) - 1) : 31;   // warp-uniform
                // ordered compose lanes start..0 (earliest tile first)
                CH acc;
                acc.L = __shfl_sync(0xffffffffu, v.L, start);
                acc.H = __shfl_sync(0xffffffffu, v.H, start);
                for (int j = start - 1; j >= 0; j--) {
                    CH b;
                    b.L = __shfl_sync(0xffffffffu, v.L, j);
                    b.H = __shfl_sync(0xffffffffu, v.H, j);
                    acc = ch_comp(acc, b);
                }
                run = ch_comp(acc, run);
                if (m) break;
                tile -= 32;
            }
            if (lane == 0) {
                CH inc = ch_comp(run, s_tot);
                g_incl[bid] = make_float2(inc.L, inc.H);
                st_flag_release(bid, FLAG_PRE);
            }
        }
        if (lane == 0) s_prefix = run;
    }
    __syncthreads();

    // exclusive prefix for this thread's first item, applied to initial state
    CH my = ch_comp(s_prefix, e);
    float s0   = __ldg(stt);
    float prev = fminf(fmaxf(s0, my.L), my.H);   // = out[base-1]

    // direct sequential recurrence, streaming stores
    float4* o = reinterpret_cast<float4*>(out + base);
#pragma unroll
    for (int q = 0; q < ITEMS / 4; q++) {
        float4 r;
        prev = fminf(fmaxf(prev, x[4 * q + 0]), x[4 * q + 0] + 1.0f); r.x = prev;
        prev = fminf(fmaxf(prev, x[4 * q + 1]), x[4 * q + 1] + 1.0f); r.y = prev;
        prev = fminf(fmaxf(prev, x[4 * q + 2]), x[4 * q + 2] + 1.0f); r.z = prev;
        prev = fminf(fmaxf(prev, x[4 * q + 3]), x[4 * q + 3] + 1.0f); r.w = prev;
        __stcs(&o[q], r);
    }

    // new_state appended after T outputs, if present
    if (base + ITEMS == n && out_size > n) out[n] = prev;
}

extern "C" void kernel_launch(void* const* d_in, const int* in_sizes, int n_in,
                              void* d_out, int out_size) {
    const float* in  = (const float*)d_in[0];   // inputs [1, T]
    const float* stt = (const float*)d_in[1];   // state  [1, 1]
    const float* kw  = (const float*)d_in[2];   // kernel [1, 1]
    float* out = (float*)d_out;

    int n  = in_sizes[0];
    int nb = n / CHUNK;                         // 2^23 / 4096 = 2048 tiles

    k_reset<<<(nb + 255) / 256, 256>>>(nb);
    k_scan<<<nb, BLOCK>>>(in, kw, stt, out, n, out_size);
}

// round 7
// speedup vs baseline: 1.3176x; 1.3176x over previous
#include <cuda_runtime.h>
#include <math_constants.h>

// PhiCell hysteresis scan: out_i = clamp(out_{i-1}, x_i, x_i + 1), x_i = in_i*k.
// Clamp-map composition is associative -> single-pass decoupled-lookback scan.
// R5: fat tiles (8192), re-read input from L2 in output phase, tree-composed
// lookback windows, and NO waiting on PRE flags (compose AGGs, walk on) so
// there is no serial propagation chain.

#define BLOCK 256
#define ITEMS 32
#define CHUNK (BLOCK * ITEMS)   // 8192 elements per tile
#define MAXB  2048

#define FLAG_INV 0
#define FLAG_AGG 1
#define FLAG_PRE 2

struct CH { float L, H; };

__device__ __forceinline__ CH ch_id() {
    CH r; r.L = -CUDART_INF_F; r.H = CUDART_INF_F; return r;
}
// compose: apply a FIRST, then b
__device__ __forceinline__ CH ch_comp(CH a, CH b) {
    CH r;
    r.L = fminf(fmaxf(a.L, b.L), b.H);
    r.H = fminf(fmaxf(a.H, b.L), b.H);
    return r;
}

// write-once descriptor slots + flag
__device__ float2 g_agg[MAXB];
__device__ float2 g_incl[MAXB];
__device__ int    g_flag[MAXB];

__device__ __forceinline__ void st_flag_release(int i, int f) {
    asm volatile("st.global.release.gpu.b32 [%0], %1;"
                 :: "l"(&g_flag[i]), "r"(f) : "memory");
}
__device__ __forceinline__ int ld_flag_acquire(int i) {
    int f;
    asm volatile("ld.global.acquire.gpu.b32 %0, [%1];"
                 : "=r"(f) : "l"(&g_flag[i]) : "memory");
    return f;
}

__device__ __forceinline__ CH warp_incl_scan(CH v, int lane) {
#pragma unroll
    for (int off = 1; off < 32; off <<= 1) {
        float pl = __shfl_up_sync(0xffffffffu, v.L, off);
        float ph = __shfl_up_sync(0xffffffffu, v.H, off);
        if (lane >= off) { CH p; p.L = pl; p.H = ph; v = ch_comp(p, v); }
    }
    return v;
}

// exclusive composite of all lower-threadIdx threads (identity for t==0)
__device__ CH block_excl_scan(CH v) {
    __shared__ CH ws[BLOCK / 32];
    int lane = threadIdx.x & 31;
    int wid  = threadIdx.x >> 5;

    CH vi = warp_incl_scan(v, lane);
    if (lane == 31) ws[wid] = vi;
    __syncthreads();
    if (wid == 0) {
        CH w = (lane < BLOCK / 32) ? ws[lane] : ch_id();
        w = warp_incl_scan(w, lane);
        if (lane < BLOCK / 32) ws[lane] = w;
    }
    __syncthreads();
    CH wp = (wid > 0) ? ws[wid - 1] : ch_id();

    float pl = __shfl_up_sync(0xffffffffu, vi.L, 1);
    float ph = __shfl_up_sync(0xffffffffu, vi.H, 1);
    CH ve = ch_id();
    if (lane > 0) { ve.L = pl; ve.H = ph; }
    return ch_comp(wp, ve);
}

// reset tile flags before each scan (graph replays reuse g_flag)
__global__ void k_reset(int nb) {
    int i = blockIdx.x * blockDim.x + threadIdx.x;
    if (i < nb) g_flag[i] = FLAG_INV;
}

__global__ void __launch_bounds__(BLOCK)
k_scan(const float* __restrict__ in, const float* __restrict__ kw,
       const float* __restrict__ stt, float* __restrict__ out,
       int n, int out_size) {
    __shared__ CH s_prefix;
    __shared__ CH s_tot;

    float k  = __ldg(kw);
    int bid  = blockIdx.x;
    int base = bid * CHUNK + threadIdx.x * ITEMS;
    const float4* p = reinterpret_cast<const float4*>(in + base);

    // ---- phase A: composite only (x not retained) ----
    CH c = ch_id();
#pragma unroll
    for (int q = 0; q < ITEMS / 4; q++) {
        float4 x4 = __ldg(&p[q]);
        float a0 = x4.x * k, a1 = x4.y * k, a2 = x4.z * k, a3 = x4.w * k;
        c.L = fminf(fmaxf(c.L, a0), a0 + 1.0f);
        c.H = fminf(fmaxf(c.H, a0), a0 + 1.0f);
        c.L = fminf(fmaxf(c.L, a1), a1 + 1.0f);
        c.H = fminf(fmaxf(c.H, a1), a1 + 1.0f);
        c.L = fminf(fmaxf(c.L, a2), a2 + 1.0f);
        c.H = fminf(fmaxf(c.H, a2), a2 + 1.0f);
        c.L = fminf(fmaxf(c.L, a3), a3 + 1.0f);
        c.H = fminf(fmaxf(c.H, a3), a3 + 1.0f);
    }

    CH e = block_excl_scan(c);   // contains __syncthreads

    // publish tile descriptor ASAP (write-once slot + release flag)
    if (threadIdx.x == BLOCK - 1) {
        CH t = ch_comp(e, c);
        s_tot = t;
        if (bid == 0) {
            g_incl[0] = make_float2(t.L, t.H);
            st_flag_release(0, FLAG_PRE);
        } else {
            g_agg[bid] = make_float2(t.L, t.H);
            st_flag_release(bid, FLAG_AGG);
        }
    }
    __syncthreads();

    // ---- lookback: warp 0, 32-wide windows, tree compose, no PRE waiting ----
    if (threadIdx.x < 32) {
        int lane = threadIdx.x;
        CH run = ch_id();
        if (bid > 0) {
            int tile = bid;
            while (true) {
                int idx = tile - 1 - lane;
                CH v; int fl;
                if (idx >= 0) {
                    // spin only on INV (predecessor always eventually aggregates)
                    do { fl = ld_flag_acquire(idx); } while (fl == FLAG_INV);
                    float2 w = (fl == FLAG_PRE) ? g_incl[idx] : g_agg[idx];
                    v.L = w.x; v.H = w.y;
                } else {
                    v = ch_id(); fl = FLAG_PRE;
                }
                unsigned m = __ballot_sync(0xffffffffu, fl == FLAG_PRE);
                int start = m ? (__ffs(m) - 1) : 31;   // warp-uniform
                // identity-pad lanes beyond start, then butterfly tree compose
                if (lane > start) v = ch_id();
#pragma unroll
                for (int off = 1; off < 32; off <<= 1) {
                    float bl = __shfl_down_sync(0xffffffffu, v.L, off);
                    float bh = __shfl_down_sync(0xffffffffu, v.H, off);
                    if (lane + off < 32) {
                        CH b; b.L = bl; b.H = bh;     // earlier tile
                        v = ch_comp(b, v);            // apply earlier first
                    }
                }
                // lane 0 now holds composite of tiles (tile-1-start .. tile-1)
                CH acc;
                acc.L = __shfl_sync(0xffffffffu, v.L, 0);
                acc.H = __shfl_sync(0xffffffffu, v.H, 0);
                run = ch_comp(acc, run);
                if (m) break;          // window contained an inclusive prefix
                tile -= 32;            // else walk further back (AGGs composed)
            }
            if (lane == 0) {
                CH inc = ch_comp(run, s_tot);
                g_incl[bid] = make_float2(inc.L, inc.H);
                st_flag_release(bid, FLAG_PRE);
            }
        }
        if (lane == 0) s_prefix = run;
    }
    __syncthreads();

    // ---- phase B: re-read input (L2-hot), apply recurrence, write ----
    CH my = ch_comp(s_prefix, e);
    float s0   = __ldg(stt);
    float prev = fminf(fmaxf(s0, my.L), my.H);   // = out[base-1]

    float4* o = reinterpret_cast<float4*>(out + base);
#pragma unroll
    for (int q = 0; q < ITEMS / 4; q++) {
        float4 x4 = __ldg(&p[q]);
        float4 r;
        float a;
        a = x4.x * k; prev = fminf(fmaxf(prev, a), a + 1.0f); r.x = prev;
        a = x4.y * k; prev = fminf(fmaxf(prev, a), a + 1.0f); r.y = prev;
        a = x4.z * k; prev = fminf(fmaxf(prev, a), a + 1.0f); r.z = prev;
        a = x4.w * k; prev = fminf(fmaxf(prev, a), a + 1.0f); r.w = prev;
        __stcs(&o[q], r);
    }

    // new_state appended after T outputs, if present
    if (base + ITEMS == n && out_size > n) out[n] = prev;
}

extern "C" void kernel_launch(void* const* d_in, const int* in_sizes, int n_in,
                              void* d_out, int out_size) {
    const float* in  = (const float*)d_in[0];   // inputs [1, T]
    const float* stt = (const float*)d_in[1];   // state  [1, 1]
    const float* kw  = (const float*)d_in[2];   // kernel [1, 1]
    float* out = (float*)d_out;

    int n  = in_sizes[0];
    int nb = n / CHUNK;                         // 2^23 / 8192 = 1024 tiles

    k_reset<<<(nb + 255) / 256, 256>>>(nb);
    k_scan<<<nb, BLOCK>>>(in, kw, stt, out, n, out_size);
}